// round 2
// baseline (speedup 1.0000x reference)
#include <cuda_runtime.h>

#define Lf 512
#define Bf 4096
#define Tt 25

// ---- scratch (device globals: no runtime allocation allowed) ----
__device__ float g_score[(size_t)Lf * Bf * Tt];   // viterbi max scores, 209.7 MB
__device__ float g_logz[Bf];
__device__ float g_num[Bf];

// ---------------------------------------------------------------------------
__global__ void init_kernel(float* out, int base) {
    int i = blockIdx.x * blockDim.x + threadIdx.x;
    if (i < Bf) g_num[i] = 0.f;
    if (i == 0 && base > 0) out[0] = 0.f;
}

// ---------------------------------------------------------------------------
// Fused forward (log-partition, scaled linear space) + Viterbi max scores.
// Block: 32 batch elements x 13 column-threads (each owns tag cols j and j+13).
__global__ __launch_bounds__(416, 1) void fwd_vit_kernel(
    const float* __restrict__ em, const float* __restrict__ trans,
    const float* __restrict__ start, const float* __restrict__ endt)
{
    __shared__ float sa[2][Tt][32];   // linear-space alpha (unnormalized), double buffered
    __shared__ float sv[2][Tt][32];   // viterbi scores, double buffered
    __shared__ float sem[32 * Tt];    // staged emissions for this step
    __shared__ float sscale[32];      // 1 / sum(alpha) of previous step

    const int tid = threadIdx.x;
    const int bi  = tid & 31;
    const int jj  = tid >> 5;          // 0..12
    const int j1  = jj;
    const int j2  = jj + 13;
    const bool v2 = (j2 < Tt);
    const int b0  = blockIdx.x * 32;
    const int b   = b0 + bi;

    // loop-invariant transition columns in registers
    float E1[Tt], E2[Tt], T1[Tt], T2[Tt];
#pragma unroll
    for (int i = 0; i < Tt; i++) {
        T1[i] = trans[i * Tt + j1];
        E1[i] = __expf(T1[i]);
        T2[i] = v2 ? trans[i * Tt + j2] : -1e30f;
        E2[i] = v2 ? __expf(T2[i]) : 0.f;
    }
    const float st1 = start[j1];
    const float st2 = v2 ? start[j2] : 0.f;

    float logacc = 0.f;   // meaningful on warp 0 (lane = bi)
    int p = 0;

    // ---- l = 0 ----
    {
        const float* src = em + (size_t)b0 * Tt;
        sem[tid] = src[tid];
        if (tid + 416 < 32 * Tt) sem[tid + 416] = src[tid + 416];
        __syncthreads();
        float e1 = sem[bi * Tt + j1];
        float s1 = st1 + e1;
        sa[0][j1][bi] = __expf(s1);
        sv[0][j1][bi] = s1;
        g_score[(size_t)b * Tt + j1] = s1;
        if (v2) {
            float e2 = sem[bi * Tt + j2];
            float s2 = st2 + e2;
            sa[0][j2][bi] = __expf(s2);
            sv[0][j2][bi] = s2;
            g_score[(size_t)b * Tt + j2] = s2;
        }
        __syncthreads();
        if (tid < 32) {
            float S = 0.f;
#pragma unroll
            for (int j = 0; j < Tt; j++) S += sa[0][j][tid];
            sscale[tid] = 1.f / S;
            logacc = __logf(S);
        }
        __syncthreads();
    }

    for (int l = 1; l < Lf; l++) {
        // stage emissions for this step (coalesced)
        const float* src = em + ((size_t)l * Bf + b0) * Tt;
        sem[tid] = src[tid];
        if (tid + 416 < 32 * Tt) sem[tid + 416] = src[tid + 416];
        __syncthreads();

        float e1 = sem[bi * Tt + j1];
        float e2 = v2 ? sem[bi * Tt + j2] : 0.f;
        float invS = sscale[bi];

        float r1 = 0.f, r2 = 0.f, m1 = -1e30f, m2 = -1e30f;
#pragma unroll
        for (int i = 0; i < Tt; i++) {
            float ai = sa[p][i][bi];
            float vi = sv[p][i][bi];
            r1 += ai * E1[i];
            r2 += ai * E2[i];
            m1 = fmaxf(m1, vi + T1[i]);
            m2 = fmaxf(m2, vi + T2[i]);
        }
        const int q = p ^ 1;
        {
            float u1 = r1 * __expf(e1) * invS;
            float s1 = m1 + e1;   // == max_i((score+trans)+em) exactly (monotone add)
            sa[q][j1][bi] = u1;
            sv[q][j1][bi] = s1;
            g_score[((size_t)l * Bf + b) * Tt + j1] = s1;
        }
        if (v2) {
            float u2 = r2 * __expf(e2) * invS;
            float s2 = m2 + e2;
            sa[q][j2][bi] = u2;
            sv[q][j2][bi] = s2;
            g_score[((size_t)l * Bf + b) * Tt + j2] = s2;
        }
        __syncthreads();
        if (tid < 32) {
            float S = 0.f;
#pragma unroll
            for (int j = 0; j < Tt; j++) S += sa[q][j][tid];
            sscale[tid] = 1.f / S;
            if (l < Lf - 1) logacc += __logf(S);
        }
        __syncthreads();
        p = q;
    }

    // final log-partition: logz = sum_{t<=510} log S_t + log( sum_j U_511[j] * e^{end_j} )
    if (tid < 32) {
        float dot = 0.f;
#pragma unroll
        for (int j = 0; j < Tt; j++) dot += sa[p][j][tid] * __expf(endt[j]);
        g_logz[b0 + tid] = logacc + __logf(dot);
    }
}

// ---------------------------------------------------------------------------
// Gold-path numerator: parallel over (batch, 16-step chunks).
__global__ void numer_kernel(const float* __restrict__ em, const int* __restrict__ tags,
                             const float* __restrict__ trans, const float* __restrict__ start,
                             const float* __restrict__ endt)
{
    int idx = blockIdx.x * blockDim.x + threadIdx.x;      // 0 .. Bf*32-1
    if (idx >= Bf * 32) return;
    int b  = idx & (Bf - 1);
    int c  = idx >> 12;                                   // chunk 0..31
    int l0 = c * 16;
    float acc = 0.f;
    int prev = 0;
    if (c > 0) prev = tags[(size_t)(l0 - 1) * Bf + b];
#pragma unroll
    for (int dl = 0; dl < 16; dl++) {
        int l  = l0 + dl;
        int tg = tags[(size_t)l * Bf + b];
        acc += em[((size_t)l * Bf + b) * Tt + tg];
        if (l == 0) acc += start[tg];
        else        acc += trans[prev * Tt + tg];
        prev = tg;
    }
    if (l0 + 16 == Lf) acc += endt[prev];
    atomicAdd(&g_num[b], acc);
}

// ---------------------------------------------------------------------------
// Backtrack: one warp per batch element, lanes = candidate previous tags.
// Argmax recomputed exactly as reference: ((score+trans)+em), first-max wins.
__global__ void backtrack_kernel(const float* __restrict__ em,
                                 const float* __restrict__ trans,
                                 const float* __restrict__ endt,
                                 float* __restrict__ out, int base)
{
    __shared__ float st[Tt * Tt];
    int tid = threadIdx.x;
    for (int i = tid; i < Tt * Tt; i += blockDim.x) st[i] = trans[i];
    __syncthreads();

    int gwarp = (blockIdx.x * blockDim.x + tid) >> 5;     // == batch index
    int lane  = tid & 31;
    int b = gwarp;                                        // grid sized so gwarp < Bf always
    bool alive = lane < Tt;

    // last tag = argmax_j(score[L-1] + end[j]) (first max)
    float v; int idx;
    {
        float s = alive ? g_score[((size_t)(Lf - 1) * Bf + b) * Tt + lane] : -3e38f;
        v   = alive ? s + endt[lane] : -3e38f;
        idx = alive ? lane : 1000;
#pragma unroll
        for (int off = 16; off; off >>= 1) {
            float ov = __shfl_down_sync(0xffffffff, v, off);
            int   oi = __shfl_down_sync(0xffffffff, idx, off);
            if (ov > v || (ov == v && oi < idx)) { v = ov; idx = oi; }
        }
    }
    int jn = __shfl_sync(0xffffffff, idx, 0);
    if (lane == 0) out[base + (size_t)(Lf - 1) * Bf + b] = (float)jn;

    for (int l = Lf - 2; l >= 0; l--) {
        float e  = alive ? em[((size_t)(l + 1) * Bf + b) * Tt + lane] : 0.f;
        float sc = alive ? g_score[((size_t)l * Bf + b) * Tt + lane] : 0.f;
        float emn = __shfl_sync(0xffffffff, e, jn);
        float t  = alive ? (sc + st[lane * Tt + jn]) + emn : -3e38f;
        int   ix = alive ? lane : 1000;
#pragma unroll
        for (int off = 16; off; off >>= 1) {
            float ov = __shfl_down_sync(0xffffffff, t, off);
            int   oi = __shfl_down_sync(0xffffffff, ix, off);
            if (ov > t || (ov == t && oi < ix)) { t = ov; ix = oi; }
        }
        jn = __shfl_sync(0xffffffff, ix, 0);
        if (lane == 0) out[base + (size_t)l * Bf + b] = (float)jn;
    }

    // nll contribution: mean over batch of (log_z - numerator)
    if (lane == 0 && base > 0) {
        float c = (g_logz[b] - g_num[b]) * (1.0f / Bf);
        atomicAdd(out, c);
    }
}

// ---------------------------------------------------------------------------
extern "C" void kernel_launch(void* const* d_in, const int* in_sizes, int n_in,
                              void* d_out, int out_size) {
    const float* em    = (const float*)d_in[0];
    const int*   tags  = (const int*)d_in[1];
    const float* trans = (const float*)d_in[2];
    const float* start = (const float*)d_in[3];
    const float* endt  = (const float*)d_in[4];
    float* out = (float*)d_out;

    // expected layout: out[0] = nll, out[1..] = best_path (L*B). Be defensive:
    int base = out_size - Lf * Bf;   // should be 1
    if (base < 0) base = 0;

    init_kernel<<<16, 256>>>(out, base);
    fwd_vit_kernel<<<Bf / 32, 416>>>(em, trans, start, endt);
    numer_kernel<<<(Bf * 32) / 256, 256>>>(em, tags, trans, start, endt);
    backtrack_kernel<<<(Bf * 32) / 256, 256>>>(em, trans, endt, out, base);
}